// round 8
// baseline (speedup 1.0000x reference)
#include <cuda_runtime.h>
#include <cuda_bf16.h>
#include <cstdint>

// Problem dims (fixed by reference)
#define T_DIM 1024
#define B_DIM 32
#define K_DIM 8
#define N_DIM 64
#define M_DIM 64
#define KN    512      // K_DIM * N_DIM
#define BK    256      // B_DIM * K_DIM
#define ROWS  32768    // T*B rows of the big GEMM
#define KTOT  1024     // real K (re|im interleaved pairs; 512 uint32 per row)
#define NTOT  128      // output cols (re|im stacked)

#define X_SZ   (T_DIM * B_DIM * K_DIM)   // 262144
#define C_SZ   (K_DIM * N_DIM * M_DIM)   // 32768
#define V_SZ   (K_DIM * N_DIM)           // 512
#define OUT_CPLX (T_DIM * B_DIM * M_DIM) // 2097152 complex values

// ---------------- scratch (static device allocations only) ----------------
__device__ float2   g_Bp[KN];
__device__ uint32_t g_Ahi[(size_t)ROWS * 512];   // 64 MiB, packed bf16x2 (re,im)
__device__ uint32_t g_Alo[(size_t)ROWS * 512];   // 64 MiB
__device__ uint32_t g_Bh[NTOT * 512];            // 256 KiB, [n][kk] K-major packed
__device__ uint32_t g_Bl[NTOT * 512];

// ---------------- PTX helpers (base sm_100 features only) ----------------
typedef unsigned long long u64;

__device__ __forceinline__ uint32_t smem_u32(const void* p) {
    uint32_t a;
    asm("{ .reg .u64 t; cvta.to.shared.u64 t, %1; cvt.u32.u64 %0, t; }" : "=r"(a) : "l"(p));
    return a;
}
__device__ __forceinline__ void ldsm_x4(uint32_t* r, uint32_t addr) {
    asm volatile("ldmatrix.sync.aligned.m8n8.x4.shared.b16 {%0,%1,%2,%3}, [%4];"
                 : "=r"(r[0]), "=r"(r[1]), "=r"(r[2]), "=r"(r[3]) : "r"(addr));
}
__device__ __forceinline__ void mma_bf16(float* d, const uint32_t* a, const uint32_t* b) {
    asm volatile("mma.sync.aligned.m16n8k16.row.col.f32.bf16.bf16.f32 "
                 "{%0,%1,%2,%3}, {%4,%5,%6,%7}, {%8,%9}, {%0,%1,%2,%3};"
                 : "+f"(d[0]), "+f"(d[1]), "+f"(d[2]), "+f"(d[3])
                 : "r"(a[0]), "r"(a[1]), "r"(a[2]), "r"(a[3]), "r"(b[0]), "r"(b[1]));
}
#define CP16(dst, src) \
    asm volatile("cp.async.cg.shared.global [%0], [%1], 16;" :: "r"(dst), "l"(src))
#define CP_COMMIT() asm volatile("cp.async.commit_group;" ::: "memory")
#define CP_WAIT(n)  asm volatile("cp.async.wait_group %0;" :: "n"(n) : "memory")

__device__ __forceinline__ uint32_t pack_bf16x2(float lo, float hi) {
    uint32_t r;
    asm("cvt.rn.bf16x2.f32 %0, %1, %2;" : "=r"(r) : "f"(hi), "f"(lo));
    return r;
}
// packed f32x2 ops
__device__ __forceinline__ u64 fma2(u64 a, u64 b, u64 c) {
    u64 d; asm("fma.rn.f32x2 %0, %1, %2, %3;" : "=l"(d) : "l"(a), "l"(b), "l"(c)); return d;
}
__device__ __forceinline__ u64 mul2(u64 a, u64 b) {
    u64 d; asm("mul.rn.f32x2 %0, %1, %2;" : "=l"(d) : "l"(a), "l"(b)); return d;
}
__device__ __forceinline__ u64 add2(u64 a, u64 b) {
    u64 d; asm("add.rn.f32x2 %0, %1, %2;" : "=l"(d) : "l"(a), "l"(b)); return d;
}
__device__ __forceinline__ u64 pk(float x, float y) {
    u64 d; asm("mov.b64 %0, {%1, %2};" : "=l"(d) : "f"(x), "f"(y)); return d;
}
__device__ __forceinline__ void upk(u64 v, float& x, float& y) {
    asm("mov.b64 {%0, %1}, %2;" : "=f"(x), "=f"(y) : "l"(v));
}

// ---------------- kernel 1: B' from lambda (fp32, parallel) ---------------
__global__ void bp_kernel(const float* __restrict__ lam_re,
                          const float* __restrict__ lam_im) {
    __shared__ float ssr[64], ssi[64];
    int idx = blockIdx.x;
    int j = idx & 63;
    int base = idx & ~63;
    int i = threadIdx.x;
    float sr = 0.f, si = 0.f;
    if (i != j) {
        float ljr = lam_re[idx], lji = lam_im[idx];
        float den = ljr * ljr + lji * lji;
        float lir = lam_re[base + i], lii = lam_im[base + i];
        float rr = (lir * ljr + lii * lji) / den;
        float ri = (lii * ljr - lir * lji) / den;
        float wr = 1.f - rr, wi = -ri;
        sr = 0.5f * logf(wr * wr + wi * wi);
        si = atan2f(wi, wr);
    }
    ssr[i] = sr; ssi[i] = si;
    __syncthreads();
    #pragma unroll
    for (int s = 32; s > 0; s >>= 1) {
        if (i < s) { ssr[i] += ssr[i + s]; ssi[i] += ssi[i + s]; }
        __syncthreads();
    }
    if (i == 0) {
        float er = expf(-ssr[0]);
        float sn, cs; sincosf(ssi[0], &sn, &cs);
        g_Bp[idx] = make_float2(er * cs, -er * sn);
    }
}

// ---------------- kernel 1b: stacked B (bf16 hi/lo, packed pairs) ---------
__global__ void bprep_kernel(const float* __restrict__ C_re,
                             const float* __restrict__ C_im) {
    int id = blockIdx.x * 256 + threadIdx.x;   // n*512 + p
    int n = id >> 9;
    int p = id & 511;
    int m = n & 63;
    float v0, v1;
    if (n < 64) { v0 = C_re[p * 64 + m]; v1 = -C_im[p * 64 + m]; }
    else        { v0 = C_im[p * 64 + m]; v1 =  C_re[p * 64 + m]; }
    uint32_t h = pack_bf16x2(v0, v1);
    float h0 = __uint_as_float(h << 16);
    float h1 = __uint_as_float(h & 0xFFFF0000u);
    g_Bh[id] = h;
    g_Bl[id] = pack_bf16x2(v0 - h0, v1 - h1);
}

// ---------------- kernel 2: fused 3-pass scan, packed f32x2 ---------------
__global__ __launch_bounds__(64) void scan_kernel(
        const float* __restrict__ x,
        const float* __restrict__ lam_re,
        const float* __restrict__ lam_im) {
    int bk = blockIdx.x;              // 0..255
    int b = bk >> 3;
    int k = bk & 7;
    int n = threadIdx.x;              // 0..63
    int kn = (k << 6) | n;

    float lr = lam_re[kn], li = lam_im[kn];
    float2 Bp = g_Bp[kn];
    u64 LR   = pk(lr, lr);
    u64 LI   = pk(-li, li);
    u64 BP2  = pk(Bp.x, Bp.y);
    u64 NEG1 = pk(-1.f, -1.f);
    u64 S1 = 0, S2 = 0, S3 = 0, P1 = 0, P2 = 0, P3 = 0;
    float a1c = 1.f, a2c = 1.f;

    __shared__ float xs[64];
    const int xoff = b * K_DIM + k;

    for (int tt = 0; tt < T_DIM; tt += 64) {
        __syncthreads();
        int tl = tt + n;
        xs[n] = (tl == 0) ? 0.f : x[(tl - 1) * BK + xoff];
        __syncthreads();
        #pragma unroll 8
        for (int j = 0; j < 64; ++j) {
            float xm1 = xs[j];
            u64 BX = mul2(BP2, pk(xm1, xm1));
            // updates use CARRIED P (= lam*s_{t-1}) and alphas
            S3 = fma2(pk(a2c, a2c), P3, BX);
            S2 = fma2(pk(a1c, a1c), P2, BX);
            S1 = add2(P1, BX);
            float s1x, s1y, s2x, s2y, s3x, s3y;
            upk(S1, s1x, s1y); upk(S2, s2x, s2y); upk(S3, s3x, s3y);
            // cmul: P = {lr,lr}*S + {-li,li}*{sy,sx}
            P1 = fma2(LI, pk(s1y, s1x), mul2(LR, S1));
            P2 = fma2(LI, pk(s2y, s2x), mul2(LR, S2));
            P3 = fma2(LI, pk(s3y, s3x), mul2(LR, S3));
            float p1x, p1y, p2x, p2y;
            upk(P1, p1x, p1y); upk(P2, p2x, p2y);
            a1c = rsqrtf(fmaf(p1y, p1y, fmaf(p1x, p1x, 1.f)));
            a2c = rsqrtf(fmaf(p2y, p2y, fmaf(p2x, p2x, 1.f)));
            // emit packed bf16 hi/lo
            uint32_t ro = (((tt + j) << 5) + b) * 512 + kn;
            uint32_t h = pack_bf16x2(s3x, s3y);
            float hre = __uint_as_float(h << 16);
            float him = __uint_as_float(h & 0xFFFF0000u);
            u64 RES = fma2(pk(hre, him), NEG1, S3);   // exact s3 - hi
            float rx, ry; upk(RES, rx, ry);
            g_Ahi[ro] = h;
            g_Alo[ro] = pack_bf16x2(rx, ry);
        }
    }
}

// ---------------- kernel 3: mma.sync bf16 GEMM, k64 chunks, 2-stage -------
// CTA 512 thr (16 warps, 8m x 2n), tile 256x128, warp tile 32x64.
// Per chunk: CP_WAIT(0) -> syncthreads -> issue kc+1 -> compute kc.
#define SROW 144                           // 128B data + 16B pad, 16B aligned
#define AH_OFF 0
#define AL_OFF (256 * SROW)                // 36864
#define BH_OFF (2 * 256 * SROW)            // 73728
#define BL_OFF (BH_OFF + 128 * SROW)       // 92160
#define STAGE_BYTES (BL_OFF + 128 * SROW)  // 110592
#define NSTAGE 2
#define NCHUNK 16                          // k64 chunks

extern __shared__ uint8_t dynSmem[];

__device__ __forceinline__ void issue_chunk(int kc, uint32_t sbuf, int rowBase,
                                            int tid) {
    int k0b = kc * 128;   // byte offset of k64 chunk within a 2048B row
    const uint8_t* gAh = (const uint8_t*)g_Ahi;
    const uint8_t* gAl = (const uint8_t*)g_Alo;
    const uint8_t* gBh = (const uint8_t*)g_Bh;
    const uint8_t* gBl = (const uint8_t*)g_Bl;
    // A: 256 rows x 128B, thread -> (row = tid>>1, half = tid&1), 4x16B each
    {
        int row = tid >> 1, half = tid & 1;
        size_t ga = (size_t)(rowBase + row) * 2048 + k0b + half * 64;
        uint32_t so = sbuf + row * SROW + half * 64;
        #pragma unroll
        for (int i = 0; i < 4; ++i) {
            CP16(so + AH_OFF + i * 16, gAh + ga + i * 16);
            CP16(so + AL_OFF + i * 16, gAl + ga + i * 16);
        }
    }
    // B: 128 rows x 128B, thread -> (row = tid>>2, q = tid&3), 2x16B each
    {
        int row = tid >> 2, q = tid & 3;
        size_t gb = (size_t)row * 2048 + k0b + q * 32;
        uint32_t so = sbuf + row * SROW + q * 32;
        #pragma unroll
        for (int i = 0; i < 2; ++i) {
            CP16(so + BH_OFF + i * 16, gBh + gb + i * 16);
            CP16(so + BL_OFF + i * 16, gBl + gb + i * 16);
        }
    }
}

__global__ __launch_bounds__(512, 1) void gemm_mma(
        const float* __restrict__ x, const float* __restrict__ D,
        const float* __restrict__ Do, float* __restrict__ out, int writeCplx) {
    __shared__ float Ds[512];
    __shared__ float doSum[64];

    int tid = threadIdx.x;
    int wid = tid >> 5, lane = tid & 31;
    int wm = wid & 7, wn = wid >> 3;          // warp grid 8m x 2n
    int rowBase = blockIdx.x * 256;

    Ds[tid] = D[tid];
    if (tid < 64) {
        float s = 0.f;
        #pragma unroll
        for (int k = 0; k < K_DIM; ++k) s += Do[k * 64 + tid];
        doSum[tid] = s;
    }

    uint32_t sbase0 = smem_u32(dynSmem);

    // ldmatrix per-thread address components
    int mi = lane >> 3;                        // 0..3
    int arow = (lane & 7) + (mi & 1) * 8;
    int acol16 = mi >> 1;
    int bnrow = (mi >> 1) * 8 + (lane & 7);
    int bk16 = mi & 1;

    float acc[2][8][4];
    #pragma unroll
    for (int mt = 0; mt < 2; ++mt)
        #pragma unroll
        for (int nt = 0; nt < 8; ++nt)
            #pragma unroll
            for (int e = 0; e < 4; ++e) acc[mt][nt][e] = 0.f;

    issue_chunk(0, sbase0, rowBase, tid);
    CP_COMMIT();

    #pragma unroll 1
    for (int kc = 0; kc < NCHUNK; ++kc) {
        CP_WAIT(0);        // my cp.asyncs for chunk kc landed
        __syncthreads();   // everyone's landed; compute(kc-1) done by all
        if (kc + 1 < NCHUNK) {
            issue_chunk(kc + 1, sbase0 + ((kc + 1) & 1) * STAGE_BYTES, rowBase, tid);
            CP_COMMIT();
        }

        uint32_t sAh = sbase0 + (kc & 1) * STAGE_BYTES;
        uint32_t sAl = sAh + AL_OFF;
        uint32_t sBh = sAh + BH_OFF;
        uint32_t sBl = sAh + BL_OFF;

        #pragma unroll
        for (int ks = 0; ks < 4; ++ks) {
            uint32_t ah[2][4], al[2][4];
            #pragma unroll
            for (int mt = 0; mt < 2; ++mt) {
                uint32_t off = (wm * 32 + mt * 16 + arow) * SROW + ks * 32 + acol16 * 16;
                ldsm_x4(ah[mt], sAh + off);
                ldsm_x4(al[mt], sAl + off);
            }
            #pragma unroll
            for (int ntp = 0; ntp < 4; ++ntp) {
                uint32_t boff = (wn * 64 + ntp * 16 + bnrow) * SROW + ks * 32 + bk16 * 16;
                uint32_t bh4[4], bl4[4];
                ldsm_x4(bh4, sBh + boff);
                ldsm_x4(bl4, sBl + boff);
                #pragma unroll
                for (int mt = 0; mt < 2; ++mt) {
                    mma_bf16(acc[mt][2 * ntp],     ah[mt], bh4);
                    mma_bf16(acc[mt][2 * ntp],     al[mt], bh4);
                    mma_bf16(acc[mt][2 * ntp],     ah[mt], bl4);
                    mma_bf16(acc[mt][2 * ntp + 1], ah[mt], bh4 + 2);
                    mma_bf16(acc[mt][2 * ntp + 1], al[mt], bh4 + 2);
                    mma_bf16(acc[mt][2 * ntp + 1], ah[mt], bl4 + 2);
                }
            }
        }
    }

    // epilogue
    int gID = lane >> 2, tg = lane & 3;
    #pragma unroll
    for (int mt = 0; mt < 2; ++mt) {
        #pragma unroll
        for (int half = 0; half < 2; ++half) {
            int R = rowBase + wm * 32 + mt * 16 + gID + half * 8;
            float xv[K_DIM];
            #pragma unroll
            for (int k = 0; k < K_DIM; ++k) xv[k] = x[R * K_DIM + k];
            #pragma unroll
            for (int nt = 0; nt < 8; ++nt) {
                #pragma unroll
                for (int e = 0; e < 2; ++e) {
                    int col = wn * 64 + nt * 8 + tg * 2 + e;
                    float a = acc[mt][nt][half * 2 + e];
                    if (wn == 0) {  // real part: add x*D + Do, scale
                        int m = col;
                        float dt = doSum[m];
                        #pragma unroll
                        for (int k = 0; k < K_DIM; ++k)
                            dt = fmaf(xv[k], Ds[k * 64 + m], dt);
                        float v = (a + dt) * 0.125f;
                        if (writeCplx) out[((size_t)R * 64 + m) * 2] = v;
                        else           out[(size_t)R * 64 + m] = v;
                    } else {        // imag part
                        int m = col - 64;
                        if (writeCplx) out[((size_t)R * 64 + m) * 2 + 1] = a * 0.125f;
                    }
                }
            }
        }
    }
}

// ---------------- launch ----------------
extern "C" void kernel_launch(void* const* d_in, const int* in_sizes, int n_in,
                              void* d_out, int out_size) {
    const float* x = nullptr;
    const float* cbuf[2] = {nullptr, nullptr};
    const float* vbuf[4] = {nullptr, nullptr, nullptr, nullptr};
    int nc = 0, nv = 0;
    for (int i = 0; i < n_in; ++i) {
        int sz = in_sizes[i];
        const float* p = (const float*)d_in[i];
        if (sz == X_SZ) x = p;
        else if (sz == C_SZ) { if (nc < 2) cbuf[nc++] = p; }
        else if (sz == V_SZ) { if (nv < 4) vbuf[nv++] = p; }
    }
    if (!x || nc < 2 || nv < 4) return;
    const float* C_re   = cbuf[0];
    const float* C_im   = cbuf[1];
    const float* lam_re = vbuf[0];
    const float* lam_im = vbuf[1];
    const float* D      = vbuf[2];
    const float* Do     = vbuf[3];

    int writeCplx = (out_size >= 2 * OUT_CPLX) ? 1 : 0;

    cudaFuncSetAttribute(gemm_mma, cudaFuncAttributeMaxDynamicSharedMemorySize,
                         NSTAGE * STAGE_BYTES);

    bp_kernel<<<KN, 64>>>(lam_re, lam_im);
    bprep_kernel<<<NTOT * 512 / 256, 256>>>(C_re, C_im);
    scan_kernel<<<BK, N_DIM>>>(x, lam_re, lam_im);
    gemm_mma<<<ROWS / 256, 512, NSTAGE * STAGE_BYTES>>>(x, D, Do, (float*)d_out, writeCplx);
}

// round 9
// speedup vs baseline: 1.1049x; 1.1049x over previous
#include <cuda_runtime.h>
#include <cuda_bf16.h>
#include <cstdint>

// Problem dims (fixed by reference)
#define T_DIM 1024
#define B_DIM 32
#define K_DIM 8
#define N_DIM 64
#define M_DIM 64
#define KN    512      // K_DIM * N_DIM
#define BK    256      // B_DIM * K_DIM
#define ROWS  32768    // T*B rows of the big GEMM
#define KTOT  1024     // real K (re|im interleaved: kk=2p -> re, 2p+1 -> im)
#define NTOT  128      // output cols (re|im stacked)

#define X_SZ   (T_DIM * B_DIM * K_DIM)   // 262144
#define C_SZ   (K_DIM * N_DIM * M_DIM)   // 32768
#define V_SZ   (K_DIM * N_DIM)           // 512
#define OUT_CPLX (T_DIM * B_DIM * M_DIM) // 2097152 complex values

// ---------------- scratch (static device allocations only) ----------------
__device__ float2 g_Bp[KN];
__device__ float2 g_Af[(size_t)ROWS * 512];   // 128 MiB, tf32-rounded (re,im) pairs
__device__ float2 g_Bf[NTOT * 512];           // 512 KiB, [n][p] K-major coeff pairs

// ---------------- PTX helpers (base sm_100 features only) ----------------
__device__ __forceinline__ uint32_t smem_u32(const void* p) {
    uint32_t a;
    asm("{ .reg .u64 t; cvta.to.shared.u64 t, %1; cvt.u32.u64 %0, t; }" : "=r"(a) : "l"(p));
    return a;
}
__device__ __forceinline__ uint32_t f2tf32(float f) {
    uint32_t u;
    asm("cvt.rna.tf32.f32 %0, %1;" : "=r"(u) : "f"(f));
    return u;
}
__device__ __forceinline__ void mma_tf32(float* d, const uint32_t* a, const uint32_t* b) {
    asm volatile("mma.sync.aligned.m16n8k8.row.col.f32.tf32.tf32.f32 "
                 "{%0,%1,%2,%3}, {%4,%5,%6,%7}, {%8,%9}, {%0,%1,%2,%3};"
                 : "+f"(d[0]), "+f"(d[1]), "+f"(d[2]), "+f"(d[3])
                 : "r"(a[0]), "r"(a[1]), "r"(a[2]), "r"(a[3]), "r"(b[0]), "r"(b[1]));
}
#define CP16(dst, src) \
    asm volatile("cp.async.cg.shared.global [%0], [%1], 16;" :: "r"(dst), "l"(src))
#define CP_COMMIT() asm volatile("cp.async.commit_group;" ::: "memory")
#define CP_WAIT(n)  asm volatile("cp.async.wait_group %0;" :: "n"(n) : "memory")

// ---------------- kernel 1: B' from lambda (fp32, parallel) ---------------
__global__ void bp_kernel(const float* __restrict__ lam_re,
                          const float* __restrict__ lam_im) {
    __shared__ float ssr[64], ssi[64];
    int idx = blockIdx.x;
    int j = idx & 63;
    int base = idx & ~63;
    int i = threadIdx.x;
    float sr = 0.f, si = 0.f;
    if (i != j) {
        float ljr = lam_re[idx], lji = lam_im[idx];
        float den = ljr * ljr + lji * lji;
        float lir = lam_re[base + i], lii = lam_im[base + i];
        float rr = (lir * ljr + lii * lji) / den;
        float ri = (lii * ljr - lir * lji) / den;
        float wr = 1.f - rr, wi = -ri;
        sr = 0.5f * logf(wr * wr + wi * wi);
        si = atan2f(wi, wr);
    }
    ssr[i] = sr; ssi[i] = si;
    __syncthreads();
    #pragma unroll
    for (int s = 32; s > 0; s >>= 1) {
        if (i < s) { ssr[i] += ssr[i + s]; ssi[i] += ssi[i + s]; }
        __syncthreads();
    }
    if (i == 0) {
        float er = expf(-ssr[0]);
        float sn, cs; sincosf(ssi[0], &sn, &cs);
        g_Bp[idx] = make_float2(er * cs, -er * sn);
    }
}

// ---------------- kernel 1b: stacked B coeffs, tf32-rounded ---------------
// row n (n<64: real out col m=n): pair p -> ( C_re[p][m], -C_im[p][m] )
// row n (n>=64: imag out col m):  pair p -> ( C_im[p][m],  C_re[p][m] )
__global__ void bprep_kernel(const float* __restrict__ C_re,
                             const float* __restrict__ C_im) {
    int id = blockIdx.x * 256 + threadIdx.x;   // n*512 + p
    int n = id >> 9;
    int p = id & 511;
    int m = n & 63;
    float v0, v1;
    if (n < 64) { v0 = C_re[p * 64 + m]; v1 = -C_im[p * 64 + m]; }
    else        { v0 = C_im[p * 64 + m]; v1 =  C_re[p * 64 + m]; }
    g_Bf[id] = make_float2(__uint_as_float(f2tf32(v0)), __uint_as_float(f2tf32(v1)));
}

// ---------------- kernel 2: fused 3-pass scan, tf32 fp32 output -----------
__global__ __launch_bounds__(64) void scan_kernel(
        const float* __restrict__ x,
        const float* __restrict__ lam_re,
        const float* __restrict__ lam_im) {
    int bk = blockIdx.x;              // 0..255
    int b = bk >> 3;
    int k = bk & 7;
    int n = threadIdx.x;              // 0..63
    int kn = (k << 6) | n;

    float lr = lam_re[kn], li = lam_im[kn];
    float2 Bp = g_Bp[kn];
    float2 s1 = make_float2(0.f, 0.f);
    float2 s2 = make_float2(0.f, 0.f);
    float2 s3 = make_float2(0.f, 0.f);
    float p1r = 0.f, p1i = 0.f, p2r = 0.f, p2i = 0.f, p3r = 0.f, p3i = 0.f;
    float a1c = 1.f, a2c = 1.f;

    __shared__ float xs[64];
    const int xoff = b * K_DIM + k;

    for (int tt = 0; tt < T_DIM; tt += 64) {
        __syncthreads();
        int tl = tt + n;
        xs[n] = (tl == 0) ? 0.f : x[(tl - 1) * BK + xoff];
        __syncthreads();
        #pragma unroll 8
        for (int j = 0; j < 64; ++j) {
            float xm1 = xs[j];
            float bxr = Bp.x * xm1, bxi = Bp.y * xm1;
            // state updates use CARRIED p (= lam*s_{t-1}) and alphas
            s3.x = fmaf(a2c, p3r, bxr);  s3.y = fmaf(a2c, p3i, bxi);
            s2.x = fmaf(a1c, p2r, bxr);  s2.y = fmaf(a1c, p2i, bxi);
            s1.x = p1r + bxr;            s1.y = p1i + bxi;
            // prepare next-step products and alphas (off critical path)
            p1r = lr * s1.x - li * s1.y;  p1i = lr * s1.y + li * s1.x;
            p2r = lr * s2.x - li * s2.y;  p2i = lr * s2.y + li * s2.x;
            p3r = lr * s3.x - li * s3.y;  p3i = lr * s3.y + li * s3.x;
            a1c = rsqrtf(1.f + p1r * p1r + p1i * p1i);
            a2c = rsqrtf(1.f + p2r * p2r + p2i * p2i);
            // emit tf32-rounded (re, im) pair
            uint32_t ro = (((tt + j) << 5) + b) * 512 + kn;
            g_Af[ro] = make_float2(__uint_as_float(f2tf32(s3.x)),
                                   __uint_as_float(f2tf32(s3.y)));
        }
    }
}

// ---------------- kernel 3: mma.sync tf32 GEMM, 3-stage, 1 sync/chunk -----
// CTA 512 thr (16 warps, 8m x 2n), tile 256x128, warp tile 32x64.
// Single pass tf32: 1024 MMA instr per CTA-chunk (vs 1536 for split-bf16).
// Per chunk: CP_WAIT -> syncthreads -> issue kc+2 -> compute kc (R7 pattern).
#define SROWF 36                            // floats per smem row (32 + 4 pad)
#define A_OFF 0
#define B_OFF (256 * SROWF * 4)             // 36864
#define STAGE_BYTES (B_OFF + 128 * SROWF * 4)  // 55296
#define NSTAGE 3
#define NCHUNK 32

extern __shared__ uint8_t dynSmem[];

__device__ __forceinline__ void issue_chunk(int kc, uint32_t sbuf, int rowBase,
                                            int tid) {
    int k0b = kc * 128;   // byte offset of k32-float chunk within 4096B row
    const uint8_t* gA = (const uint8_t*)g_Af;
    const uint8_t* gB = (const uint8_t*)g_Bf;
    // A: 256 rows x 128B; thread -> (row = tid>>1, half = tid&1), 4x16B
    {
        int row = tid >> 1, half = tid & 1;
        size_t ga = (size_t)(rowBase + row) * 4096 + k0b + half * 64;
        uint32_t so = sbuf + A_OFF + row * (SROWF * 4) + half * 64;
        #pragma unroll
        for (int i = 0; i < 4; ++i) CP16(so + i * 16, gA + ga + i * 16);
    }
    // B: 128 rows x 128B; thread -> (row = tid>>2, q = tid&3), 2x16B
    {
        int row = tid >> 2, q = tid & 3;
        size_t gb = (size_t)row * 4096 + k0b + q * 32;
        uint32_t so = sbuf + B_OFF + row * (SROWF * 4) + q * 32;
        #pragma unroll
        for (int i = 0; i < 2; ++i) CP16(so + i * 16, gB + gb + i * 16);
    }
}

__global__ __launch_bounds__(512, 1) void gemm_mma(
        const float* __restrict__ x, const float* __restrict__ D,
        const float* __restrict__ Do, float* __restrict__ out, int writeCplx) {
    __shared__ float Ds[512];
    __shared__ float doSum[64];

    int tid = threadIdx.x;
    int wid = tid >> 5, lane = tid & 31;
    int wm = wid & 7, wn = wid >> 3;          // warp grid 8m x 2n
    int rowBase = blockIdx.x * 256;

    Ds[tid] = D[tid];
    if (tid < 64) {
        float s = 0.f;
        #pragma unroll
        for (int k = 0; k < K_DIM; ++k) s += Do[k * 64 + tid];
        doSum[tid] = s;
    }

    uint32_t sbase0 = smem_u32(dynSmem);
    int gID = lane >> 2, tig = lane & 3;       // fragment coords

    float acc[2][8][4];
    #pragma unroll
    for (int mt = 0; mt < 2; ++mt)
        #pragma unroll
        for (int nt = 0; nt < 8; ++nt)
            #pragma unroll
            for (int e = 0; e < 4; ++e) acc[mt][nt][e] = 0.f;

    issue_chunk(0, sbase0, rowBase, tid);
    CP_COMMIT();
    issue_chunk(1, sbase0 + STAGE_BYTES, rowBase, tid);
    CP_COMMIT();

    int buf = 0;
    #pragma unroll 1
    for (int kc = 0; kc < NCHUNK; ++kc) {
        if (kc + 1 < NCHUNK) { CP_WAIT(1); } else { CP_WAIT(0); }
        __syncthreads();   // all threads: chunk kc landed; compute(kc-1) done
        if (kc + 2 < NCHUNK) {
            int nb = buf + 2; if (nb >= NSTAGE) nb -= NSTAGE;
            issue_chunk(kc + 2, sbase0 + nb * STAGE_BYTES, rowBase, tid);
            CP_COMMIT();
        }

        const float* sA = (const float*)(dynSmem + buf * STAGE_BYTES + A_OFF);
        const float* sB = (const float*)(dynSmem + buf * STAGE_BYTES + B_OFF);

        #pragma unroll
        for (int ks = 0; ks < 4; ++ks) {
            int kk = ks * 8 + tig;
            uint32_t af[2][4];
            #pragma unroll
            for (int mt = 0; mt < 2; ++mt) {
                const float* ar = sA + (wm * 32 + mt * 16 + gID) * SROWF;
                af[mt][0] = __float_as_uint(ar[kk]);
                af[mt][1] = __float_as_uint(ar[8 * SROWF + kk]);
                af[mt][2] = __float_as_uint(ar[kk + 4]);
                af[mt][3] = __float_as_uint(ar[8 * SROWF + kk + 4]);
            }
            #pragma unroll
            for (int nt = 0; nt < 8; ++nt) {
                const float* br = sB + (wn * 64 + nt * 8 + gID) * SROWF;
                uint32_t bf[2];
                bf[0] = __float_as_uint(br[kk]);
                bf[1] = __float_as_uint(br[kk + 4]);
                mma_tf32(acc[0][nt], af[0], bf);
                mma_tf32(acc[1][nt], af[1], bf);
            }
        }
        ++buf; if (buf >= NSTAGE) buf = 0;
    }

    // epilogue (fragment layout same as m16n8 f16: c0/c1 row gID, c2/c3 row gID+8)
    #pragma unroll
    for (int mt = 0; mt < 2; ++mt) {
        #pragma unroll
        for (int half = 0; half < 2; ++half) {
            int R = rowBase + wm * 32 + mt * 16 + gID + half * 8;
            float xv[K_DIM];
            #pragma unroll
            for (int k = 0; k < K_DIM; ++k) xv[k] = x[R * K_DIM + k];
            #pragma unroll
            for (int nt = 0; nt < 8; ++nt) {
                #pragma unroll
                for (int e = 0; e < 2; ++e) {
                    int col = wn * 64 + nt * 8 + tig * 2 + e;
                    float a = acc[mt][nt][half * 2 + e];
                    if (wn == 0) {  // real part: add x*D + Do, scale
                        int m = col;
                        float dt = doSum[m];
                        #pragma unroll
                        for (int k = 0; k < K_DIM; ++k)
                            dt = fmaf(xv[k], Ds[k * 64 + m], dt);
                        float v = (a + dt) * 0.125f;
                        if (writeCplx) out[((size_t)R * 64 + m) * 2] = v;
                        else           out[(size_t)R * 64 + m] = v;
                    } else {        // imag part
                        int m = col - 64;
                        if (writeCplx) out[((size_t)R * 64 + m) * 2 + 1] = a * 0.125f;
                    }
                }
            }
        }
    }
}

// ---------------- launch ----------------
extern "C" void kernel_launch(void* const* d_in, const int* in_sizes, int n_in,
                              void* d_out, int out_size) {
    const float* x = nullptr;
    const float* cbuf[2] = {nullptr, nullptr};
    const float* vbuf[4] = {nullptr, nullptr, nullptr, nullptr};
    int nc = 0, nv = 0;
    for (int i = 0; i < n_in; ++i) {
        int sz = in_sizes[i];
        const float* p = (const float*)d_in[i];
        if (sz == X_SZ) x = p;
        else if (sz == C_SZ) { if (nc < 2) cbuf[nc++] = p; }
        else if (sz == V_SZ) { if (nv < 4) vbuf[nv++] = p; }
    }
    if (!x || nc < 2 || nv < 4) return;
    const float* C_re   = cbuf[0];
    const float* C_im   = cbuf[1];
    const float* lam_re = vbuf[0];
    const float* lam_im = vbuf[1];
    const float* D      = vbuf[2];
    const float* Do     = vbuf[3];

    int writeCplx = (out_size >= 2 * OUT_CPLX) ? 1 : 0;

    cudaFuncSetAttribute(gemm_mma, cudaFuncAttributeMaxDynamicSharedMemorySize,
                         NSTAGE * STAGE_BYTES);

    bp_kernel<<<KN, 64>>>(lam_re, lam_im);
    bprep_kernel<<<NTOT * 512 / 256, 256>>>(C_re, C_im);
    scan_kernel<<<BK, N_DIM>>>(x, lam_re, lam_im);
    gemm_mma<<<ROWS / 256, 512, NSTAGE * STAGE_BYTES>>>(x, D, Do, (float*)d_out, writeCplx);
}